// round 8
// baseline (speedup 1.0000x reference)
#include <cuda_runtime.h>
#include <cuda_bf16.h>
#include <cstdint>

// ---------------------------------------------------------------------------
// STARDNN on GB300.  R8: mma.sync bf16x3 (proven R7) with
//  - weights pre-split once in gmem: bf16 hi/lo, k-pair interleaved uint32
//    words [s][K/2][N]  -> B fragments become single lds.32
//  - K-chunk 32, 512 threads (16 warps, 4x4 warp grid, 32x32 warp tiles)
//  - warp-aggregated bucket atomics
// A (activations) stay fp32 end-to-end (proven path), split in-kernel.
// ---------------------------------------------------------------------------

#define NS    7
#define MAXB  16384
#define D0    512
#define D1    512
#define D2    256
#define D3    64

// ------------------------- device scratch (no allocs) ----------------------
__device__ int   g_count[NS];
__device__ int   g_offset[NS];
__device__ int   g_cursor[NS];
__device__ int   g_perm[MAXB];
__device__ __align__(16) float g_h1[MAXB * D1];
__device__ __align__(16) float g_h2[MAXB * D2];
// pre-split gate-scaled weights: word (s, k>>1, n) = bf16(W*gW)[k] | [k+1]<<16
__device__ __align__(16) uint32_t g_SWh0[NS * (D0 / 2) * D1], g_SWl0[NS * (D0 / 2) * D1];
__device__ __align__(16) uint32_t g_SWh1[NS * (D1 / 2) * D2], g_SWl1[NS * (D1 / 2) * D2];
__device__ __align__(16) uint32_t g_SWh2[NS * (D2 / 2) * D3], g_SWl2[NS * (D2 / 2) * D3];

// ------------------------------ helpers ------------------------------------
#define MMA_BF16(d, a, b) \
    asm volatile("mma.sync.aligned.m16n8k16.row.col.f32.bf16.bf16.f32 " \
                 "{%0,%1,%2,%3}, {%4,%5,%6,%7}, {%8,%9}, {%0,%1,%2,%3};" \
                 : "+f"((d)[0]), "+f"((d)[1]), "+f"((d)[2]), "+f"((d)[3]) \
                 : "r"((a)[0]), "r"((a)[1]), "r"((a)[2]), "r"((a)[3]), \
                   "r"((b)[0]), "r"((b)[1]))

__device__ __forceinline__ void bsplit(float v, __nv_bfloat16& h, __nv_bfloat16& l) {
    h = __float2bfloat16(v);
    l = __float2bfloat16(v - __bfloat162float(h));
}

__device__ __forceinline__ uint32_t pack2(__nv_bfloat16 a, __nv_bfloat16 b) {
    union { __nv_bfloat16 h[2]; uint32_t u; } t;
    t.h[0] = a; t.h[1] = b;
    return t.u;
}

__device__ __forceinline__ void split4(float4 v, uint2& hi, uint2& lo) {
    __nv_bfloat16 h0, l0, h1, l1, h2, l2, h3, l3;
    bsplit(v.x, h0, l0); bsplit(v.y, h1, l1);
    bsplit(v.z, h2, l2); bsplit(v.w, h3, l3);
    hi.x = pack2(h0, h1); hi.y = pack2(h2, h3);
    lo.x = pack2(l0, l1); lo.y = pack2(l2, l3);
}

// ------------------------------ bucketing ----------------------------------
__device__ __forceinline__ int scene_at(const int* __restrict__ p, int b, bool is64) {
    int v = is64 ? p[2 * b] : p[b];
    int s = v - 1;
    return (s < 0) ? 0 : (s >= NS ? NS - 1 : s);
}

__global__ void k_init() {
    if (threadIdx.x < NS) g_count[threadIdx.x] = 0;
}

__global__ void k_count(const int* __restrict__ scene, int B) {
    int b = blockIdx.x * blockDim.x + threadIdx.x;
    bool is64 = (scene[1] == 0);
    int s = (b < B) ? scene_at(scene, b, is64) : -1;
#pragma unroll
    for (int ss = 0; ss < NS; ss++) {
        unsigned m = __ballot_sync(0xffffffffu, s == ss);
        if ((threadIdx.x & 31) == 0 && m)
            atomicAdd(&g_count[ss], __popc(m));
    }
}

__global__ void k_scan() {
    int off = 0;
    for (int s = 0; s < NS; s++) {
        g_offset[s] = off;
        g_cursor[s] = off;
        off += g_count[s];
    }
}

__global__ void k_scatter(const int* __restrict__ scene, int B) {
    int b = blockIdx.x * blockDim.x + threadIdx.x;
    bool is64 = (scene[1] == 0);
    int s = (b < B) ? scene_at(scene, b, is64) : -1;
    int lane = threadIdx.x & 31;
#pragma unroll
    for (int ss = 0; ss < NS; ss++) {
        unsigned m = __ballot_sync(0xffffffffu, s == ss);
        if (s == ss) {
            int leader = __ffs(m) - 1;
            int base = 0;
            if (lane == leader) base = atomicAdd(&g_cursor[ss], __popc(m));
            base = __shfl_sync(m, base, leader);
            int rank = __popc(m & ((1u << lane) - 1));
            g_perm[base + rank] = b;
        }
    }
}

// weight prep: SW[s][k][n] = W[s][k][n]*gW[k][n], bf16 hi/lo, k-pair packed
template <int KD, int ND>
__global__ __launch_bounds__(256) void k_splitw(const float* __restrict__ W,
                                                const float* __restrict__ gW,
                                                uint32_t* __restrict__ SWh,
                                                uint32_t* __restrict__ SWl) {
    const int TOT = (KD / 2) * ND;
    int stride = gridDim.x * blockDim.x;
    for (int j = blockIdx.x * blockDim.x + threadIdx.x; j < TOT; j += stride) {
        int k2 = j / ND, n = j % ND;
        size_t i0 = (size_t)(2 * k2) * ND + n;
        size_t i1 = i0 + ND;
        float ga = gW[i0], gb = gW[i1];
#pragma unroll
        for (int s = 0; s < NS; s++) {
            size_t wb = (size_t)s * KD * ND;
            float v0 = W[wb + i0] * ga;
            float v1 = W[wb + i1] * gb;
            __nv_bfloat16 h0, l0, h1, l1;
            bsplit(v0, h0, l0);
            bsplit(v1, h1, l1);
            SWh[(size_t)s * TOT + j] = pack2(h0, h1);
            SWl[(size_t)s * TOT + j] = pack2(l0, l1);
        }
    }
}

// ------------------------------ bf16x3 GEMM --------------------------------
// 512 threads, CTA tile 128 x BN, warp grid 4x4 (warp tile 32 x BN/4).
// K in chunks of 32 (two k16 mma steps per barrier), double-buffered via
// register staging (NO cp.async / NO ldmatrix).
// A smem: 128 rows x 64B bf16 + 16B pad (AROWB=80), hi/lo planes.
//   frag lds.32 banks: (m row)*(20 words)+tg -> all 32 distinct per warp.
// B smem: k-pair rows [16][BN words] +8 pad words (BROWW=BN+8 == 8 mod 32).
//   frag b[0] = word[tg+ks/2][n], b[1] = word[tg+4+ks/2][n]: single lds.32,
//   banks tg*8+g -> all 32 distinct per warp.
template <int LAYER, int K, int NF, int BN, bool RELU>
__global__ __launch_bounds__(512) void k_gemm(const float* __restrict__ xin,
                                              float* __restrict__ xout,
                                              const uint32_t* __restrict__ SWh,
                                              const uint32_t* __restrict__ SWl,
                                              const float* __restrict__ bias,
                                              const float* __restrict__ gbias,
                                              int B) {
    constexpr int MI = 2;                    // warp tile m = 32
    constexpr int NI = BN / 4 / 8;           // warp tile n = BN/4
    constexpr int NCH = K / 32;
    constexpr int AROWB = 80;                // 32 bf16 (64B) + 16B pad
    constexpr int APL = 128 * AROWB;         // 10240
    constexpr int BROWW = BN + 8;            // words; == 8 mod 32
    constexpr int BROWB = BROWW * 4;
    constexpr int BPL = 16 * BROWB;          // 16 k-pair rows per chunk
    constexpr int BUFSZ = 2 * APL + 2 * BPL;
    constexpr int BU4 = 4 * BN;              // uint4 loads per B plane chunk

    extern __shared__ char sm[];

    const int s   = blockIdx.z;
    const int cnt = g_count[s];
    const int m0  = blockIdx.x * 128;
    if (m0 >= cnt) return;
    const int off  = g_offset[s];
    const int rows = min(128, cnt - m0);
    const int n0   = blockIdx.y * BN;
    const int tid  = threadIdx.x;

    const float* in = (LAYER == 0) ? xin : (LAYER == 1 ? g_h1 : g_h2);
    float*      out = (LAYER == 2) ? xout : (LAYER == 0 ? g_h1 : g_h2);

    // ---- A staging descriptors: 2 float4 per thread per chunk ----
    const int aq = (tid & 7) * 4;            // float col 0..28
    const float* aptr[2];
    uint32_t adst[2];
#pragma unroll
    for (int i = 0; i < 2; i++) {
        int r = (tid >> 3) + i * 64;         // 0..127
        int pr = off + m0 + ((r < rows) ? r : 0);
        if (pr > B - 1) pr = B - 1;
        int grow = (LAYER == 0) ? g_perm[pr] : pr;
        aptr[i] = in + (size_t)grow * K + aq;
        adst[i] = (uint32_t)r * AROWB + aq * 2;
    }
    // ---- B staging: <=1 uint4 per plane per thread per chunk ----
    const bool bact = (tid < BU4);
    const uint32_t* bsrcH = nullptr;
    const uint32_t* bsrcL = nullptr;
    uint32_t bdst = 0;
    if (bact) {
        int k2 = tid / (BN / 4);             // 0..15
        int ncol = (tid % (BN / 4)) * 4;
        size_t w = ((size_t)s * (K / 2) + k2) * NF + n0 + ncol;
        bsrcH = SWh + w;
        bsrcL = SWl + w;
        bdst = (uint32_t)k2 * BROWB + ncol * 4;
    }

    const int lane = tid & 31, w = tid >> 5;
    const int wm = (w >> 2) * 32;            // 4 warp rows
    const int wn = (w & 3) * (BN / 4);       // 4 warp cols
    const int g  = lane >> 2, tg = lane & 3;

    float acc[MI][NI][4];
#pragma unroll
    for (int mi = 0; mi < MI; mi++)
#pragma unroll
        for (int ni = 0; ni < NI; ni++)
#pragma unroll
            for (int e = 0; e < 4; e++) acc[mi][ni][e] = 0.f;

    float4 aS[2];
    uint4 bSh, bSl;

    // ---- prologue: stage chunk 0 into buffer 0 ----
#pragma unroll
    for (int i = 0; i < 2; i++) aS[i] = *(const float4*)(aptr[i]);
    if (bact) {
        bSh = *(const uint4*)(bsrcH);
        bSl = *(const uint4*)(bsrcL);
    }
#pragma unroll
    for (int i = 0; i < 2; i++) {
        uint2 hi, lo;
        split4(aS[i], hi, lo);
        *(uint2*)(sm + adst[i])       = hi;
        *(uint2*)(sm + adst[i] + APL) = lo;
    }
    if (bact) {
        *(uint4*)(sm + 2 * APL + bdst)       = bSh;
        *(uint4*)(sm + 2 * APL + bdst + BPL) = bSl;
    }
    __syncthreads();

    for (int c = 0; c < NCH; c++) {
        // prefetch chunk c+1 (global latency overlaps mma below)
        if (c + 1 < NCH) {
            const int k1 = (c + 1) * 32;
#pragma unroll
            for (int i = 0; i < 2; i++) aS[i] = *(const float4*)(aptr[i] + k1);
            if (bact) {
                const size_t adv = (size_t)(c + 1) * 16 * NF;
                bSh = *(const uint4*)(bsrcH + adv);
                bSl = *(const uint4*)(bsrcL + adv);
            }
        }

        const char* Ab = sm + (c & 1) * BUFSZ;
        const char* Bb = Ab + 2 * APL;

#pragma unroll
        for (int ks = 0; ks < 32; ks += 16) {
            uint32_t ah[MI][4], al[MI][4], bh[NI][2], bl[NI][2];
#pragma unroll
            for (int mi = 0; mi < MI; mi++) {
                uint32_t base = (uint32_t)(wm + mi * 16 + g) * AROWB + ks * 2 + 4 * tg;
                ah[mi][0] = *(const uint32_t*)(Ab + base);
                ah[mi][1] = *(const uint32_t*)(Ab + base + 8 * AROWB);
                ah[mi][2] = *(const uint32_t*)(Ab + base + 16);
                ah[mi][3] = *(const uint32_t*)(Ab + base + 8 * AROWB + 16);
                al[mi][0] = *(const uint32_t*)(Ab + base + APL);
                al[mi][1] = *(const uint32_t*)(Ab + base + APL + 8 * AROWB);
                al[mi][2] = *(const uint32_t*)(Ab + base + APL + 16);
                al[mi][3] = *(const uint32_t*)(Ab + base + APL + 8 * AROWB + 16);
            }
#pragma unroll
            for (int ni = 0; ni < NI; ni++) {
                uint32_t wv = ((uint32_t)(ks >> 1) + tg) * BROWW + wn + ni * 8 + g;
                bh[ni][0] = *(const uint32_t*)(Bb + 4 * wv);
                bh[ni][1] = *(const uint32_t*)(Bb + 4 * (wv + 4 * BROWW));
                bl[ni][0] = *(const uint32_t*)(Bb + BPL + 4 * wv);
                bl[ni][1] = *(const uint32_t*)(Bb + BPL + 4 * (wv + 4 * BROWW));
            }
#pragma unroll
            for (int mi = 0; mi < MI; mi++)
#pragma unroll
                for (int ni = 0; ni < NI; ni++) {
                    MMA_BF16(acc[mi][ni], ah[mi], bh[ni]);
                    MMA_BF16(acc[mi][ni], ah[mi], bl[ni]);
                    MMA_BF16(acc[mi][ni], al[mi], bh[ni]);
                }
        }

        // store prefetched chunk into the other buffer
        if (c + 1 < NCH) {
            char* D = sm + ((c + 1) & 1) * BUFSZ;
#pragma unroll
            for (int i = 0; i < 2; i++) {
                uint2 hi, lo;
                split4(aS[i], hi, lo);
                *(uint2*)(D + adst[i])       = hi;
                *(uint2*)(D + adst[i] + APL) = lo;
            }
            if (bact) {
                *(uint4*)(D + 2 * APL + bdst)       = bSh;
                *(uint4*)(D + 2 * APL + bdst + BPL) = bSl;
            }
        }
        __syncthreads();
    }

    // ----------------------------- epilogue --------------------------------
    const float* bs = bias + (size_t)s * NF + n0;
    const float* gb = gbias + n0;
#pragma unroll
    for (int mi = 0; mi < MI; mi++) {
        const int rbase = wm + mi * 16 + g;
#pragma unroll
        for (int ni = 0; ni < NI; ni++) {
            const int c0 = wn + ni * 8 + 2 * tg;
            const float bv0 = bs[c0] + gb[c0];
            const float bv1 = bs[c0 + 1] + gb[c0 + 1];
#pragma unroll
            for (int half = 0; half < 2; half++) {
                const int r = rbase + half * 8;
                if (r < rows) {
                    float v0 = acc[mi][ni][half * 2 + 0] + bv0;
                    float v1 = acc[mi][ni][half * 2 + 1] + bv1;
                    if (RELU) { v0 = fmaxf(v0, 0.f); v1 = fmaxf(v1, 0.f); }
                    const int prow = off + m0 + r;
                    const int orow = (LAYER == 2) ? g_perm[prow] : prow;
                    *(float2*)(out + (size_t)orow * NF + n0 + c0) = make_float2(v0, v1);
                }
            }
        }
    }
}

// ---------------------------------------------------------------------------
extern "C" void kernel_launch(void* const* d_in, const int* in_sizes, int n_in,
                              void* d_out, int out_size) {
    const float* x     = (const float*)d_in[0];
    const int*   scene = (const int*)d_in[1];   // int32 or int64, auto-detected
    const float* W0  = (const float*)d_in[2];
    const float* b0  = (const float*)d_in[3];
    const float* gW0 = (const float*)d_in[4];
    const float* gb0 = (const float*)d_in[5];
    const float* W1  = (const float*)d_in[6];
    const float* b1  = (const float*)d_in[7];
    const float* gW1 = (const float*)d_in[8];
    const float* gb1 = (const float*)d_in[9];
    const float* W2  = (const float*)d_in[10];
    const float* b2  = (const float*)d_in[11];
    const float* gW2 = (const float*)d_in[12];
    const float* gb2 = (const float*)d_in[13];
    float* out = (float*)d_out;

    const int B = in_sizes[1];
    const int mtiles = (B + 127) / 128;

    // smem: L0/L1: 2*(2*10240 + 2*16*(136*4)) = 75776; L2: 2*(20480+2*16*288)=59392
    const int SM_L01 = 2 * (2 * 128 * 80 + 2 * 16 * (128 + 8) * 4);
    const int SM_L2  = 2 * (2 * 128 * 80 + 2 * 16 * (64 + 8) * 4);

    cudaFuncSetAttribute(k_gemm<0, D0, D1, 128, true >,
                         cudaFuncAttributeMaxDynamicSharedMemorySize, SM_L01);
    cudaFuncSetAttribute(k_gemm<1, D1, D2, 128, true >,
                         cudaFuncAttributeMaxDynamicSharedMemorySize, SM_L01);
    cudaFuncSetAttribute(k_gemm<2, D2, D3,  64, false>,
                         cudaFuncAttributeMaxDynamicSharedMemorySize, SM_L2);

    k_init<<<1, 32>>>();
    k_count<<<(B + 255) / 256, 256>>>(scene, B);
    k_scan<<<1, 1>>>();
    k_scatter<<<(B + 255) / 256, 256>>>(scene, B);

    k_splitw<D0, D1><<<512, 256>>>(W0, gW0, g_SWh0, g_SWl0);
    k_splitw<D1, D2><<<256, 256>>>(W1, gW1, g_SWh1, g_SWl1);
    k_splitw<D2, D3><<<64, 256>>>(W2, gW2, g_SWh2, g_SWl2);

    k_gemm<0, D0, D1, 128, true ><<<dim3(mtiles, D1 / 128, NS), 512, SM_L01>>>(
        x, nullptr, g_SWh0, g_SWl0, b0, gb0, B);
    k_gemm<1, D1, D2, 128, true ><<<dim3(mtiles, D2 / 128, NS), 512, SM_L01>>>(
        nullptr, nullptr, g_SWh1, g_SWl1, b1, gb1, B);
    k_gemm<2, D2, D3, 64, false><<<dim3(mtiles, 1, NS), 512, SM_L2>>>(
        nullptr, out, g_SWh2, g_SWl2, b2, gb2, B);
}

// round 9
// speedup vs baseline: 1.0029x; 1.0029x over previous
#include <cuda_runtime.h>
#include <cuda_bf16.h>
#include <cstdint>

// ---------------------------------------------------------------------------
// STARDNN on GB300.  R9 = R7 (229.6us, proven) + ONE change:
// weights pre-split to bf16 hi/lo in gmem, k-pair packed uint32 [s][K/2][N].
// B fragments become single lds.32; all B conversion ALU leaves the mainloop.
// Everything else (256 threads, tiles, A path, bucketing) is R7 verbatim.
// ---------------------------------------------------------------------------

#define NS    7
#define MAXB  16384
#define D0    512
#define D1    512
#define D2    256
#define D3    64

// scratch (allocation-free: __device__ globals)
__device__ int   g_count[NS];
__device__ int   g_offset[NS];
__device__ int   g_cursor[NS];
__device__ int   g_perm[MAXB];
__device__ __align__(16) float g_h1[MAXB * D1];
__device__ __align__(16) float g_h2[MAXB * D2];
// pre-split gate-scaled weights: word (s, k>>1, n) = bf16(W*gW)[k] | [k+1]<<16
__device__ __align__(16) uint32_t g_SWh0[NS * (D0 / 2) * D1], g_SWl0[NS * (D0 / 2) * D1];
__device__ __align__(16) uint32_t g_SWh1[NS * (D1 / 2) * D2], g_SWl1[NS * (D1 / 2) * D2];
__device__ __align__(16) uint32_t g_SWh2[NS * (D2 / 2) * D3], g_SWl2[NS * (D2 / 2) * D3];

// ------------------------------ helpers ------------------------------------
#define MMA_BF16(d, a, b) \
    asm volatile("mma.sync.aligned.m16n8k16.row.col.f32.bf16.bf16.f32 " \
                 "{%0,%1,%2,%3}, {%4,%5,%6,%7}, {%8,%9}, {%0,%1,%2,%3};" \
                 : "+f"((d)[0]), "+f"((d)[1]), "+f"((d)[2]), "+f"((d)[3]) \
                 : "r"((a)[0]), "r"((a)[1]), "r"((a)[2]), "r"((a)[3]), \
                   "r"((b)[0]), "r"((b)[1]))

__device__ __forceinline__ void bsplit(float v, __nv_bfloat16& h, __nv_bfloat16& l) {
    h = __float2bfloat16(v);
    l = __float2bfloat16(v - __bfloat162float(h));
}

__device__ __forceinline__ uint32_t pack2(__nv_bfloat16 a, __nv_bfloat16 b) {
    union { __nv_bfloat16 h[2]; uint32_t u; } t;
    t.h[0] = a; t.h[1] = b;
    return t.u;
}

__device__ __forceinline__ void split4(float4 v, uint2& hi, uint2& lo) {
    __nv_bfloat16 h0, l0, h1, l1, h2, l2, h3, l3;
    bsplit(v.x, h0, l0); bsplit(v.y, h1, l1);
    bsplit(v.z, h2, l2); bsplit(v.w, h3, l3);
    hi.x = pack2(h0, h1); hi.y = pack2(h2, h3);
    lo.x = pack2(l0, l1); lo.y = pack2(l2, l3);
}

// ------------------------------ bucketing (R7 verbatim) --------------------
__device__ __forceinline__ int scene_at(const int* __restrict__ p, int b, bool is64) {
    int v = is64 ? p[2 * b] : p[b];
    int s = v - 1;
    return (s < 0) ? 0 : (s >= NS ? NS - 1 : s);
}

__global__ void k_init() {
    if (threadIdx.x < NS) g_count[threadIdx.x] = 0;
}

__global__ void k_count(const int* __restrict__ scene, int B) {
    int b = blockIdx.x * blockDim.x + threadIdx.x;
    if (b < B) {
        bool is64 = (scene[1] == 0);
        atomicAdd(&g_count[scene_at(scene, b, is64)], 1);
    }
}

__global__ void k_scan() {
    int off = 0;
    for (int s = 0; s < NS; s++) {
        g_offset[s] = off;
        g_cursor[s] = off;
        off += g_count[s];
    }
}

__global__ void k_scatter(const int* __restrict__ scene, int B) {
    int b = blockIdx.x * blockDim.x + threadIdx.x;
    if (b < B) {
        bool is64 = (scene[1] == 0);
        int s = scene_at(scene, b, is64);
        int pos = atomicAdd(&g_cursor[s], 1);
        g_perm[pos] = b;
    }
}

// weight prep: SW[s][k][n] = W[s][k][n]*gW[k][n], bf16 hi/lo, k-pair packed
template <int KD, int ND>
__global__ __launch_bounds__(256) void k_splitw(const float* __restrict__ W,
                                                const float* __restrict__ gW,
                                                uint32_t* __restrict__ SWh,
                                                uint32_t* __restrict__ SWl) {
    const int TOT = (KD / 2) * ND;
    int stride = gridDim.x * blockDim.x;
    for (int j = blockIdx.x * blockDim.x + threadIdx.x; j < TOT; j += stride) {
        int k2 = j / ND, n = j % ND;
        size_t i0 = (size_t)(2 * k2) * ND + n;
        size_t i1 = i0 + ND;
        float ga = gW[i0], gb = gW[i1];
#pragma unroll
        for (int s = 0; s < NS; s++) {
            size_t wb = (size_t)s * KD * ND;
            float v0 = W[wb + i0] * ga;
            float v1 = W[wb + i1] * gb;
            __nv_bfloat16 h0, l0, h1, l1;
            bsplit(v0, h0, l0);
            bsplit(v1, h1, l1);
            SWh[(size_t)s * TOT + j] = pack2(h0, h1);
            SWl[(size_t)s * TOT + j] = pack2(l0, l1);
        }
    }
}

// ------------------------------ bf16x3 GEMM --------------------------------
// R7 geometry: 256 threads, CTA 128 x BN, warp grid 2x4 (warp tile 64 x BN/4),
// K in chunks of 16, register-staged double buffer, one barrier per chunk.
// A smem: [128][16] bf16 rows, ROWB=48, hi/lo planes (fp32 in, split at stage).
// B smem: 8 k-pair rows x BN packed words, row stride BROWW=BN+8 (==8 mod 32).
//   B fragment regs: b[0]=word[tg][col], b[1]=word[tg+4][col], col=wn+ni*8+g
//   -> banks tg*8+g: all 32 distinct; single lds.32 per register.
template <int LAYER, int K, int NF, int BN, bool RELU>
__global__ __launch_bounds__(256) void k_gemm(const float* __restrict__ xin,
                                              float* __restrict__ xout,
                                              const uint32_t* __restrict__ SWh,
                                              const uint32_t* __restrict__ SWl,
                                              const float* __restrict__ bias,
                                              const float* __restrict__ gbias,
                                              int B) {
    constexpr int MI = 4;                 // WM=64 -> 4 m16 tiles
    constexpr int NI = BN / 4 / 8;        // WN=BN/4 -> NI n8 tiles
    constexpr int NCH = K / 16;
    constexpr int ROWB = 48;
    constexpr int APL = 128 * ROWB;       // 6144
    constexpr int BROWW = BN + 8;         // words, == 8 mod 32
    constexpr int BROWB = BROWW * 4;
    constexpr int BPL = 8 * BROWB;        // 8 k-pair rows per chunk
    constexpr int BUFSZ = 2 * APL + 2 * BPL;
    constexpr int BU4 = 2 * BN;           // uint4 loads per B plane per chunk

    extern __shared__ char sm[];

    const int s   = blockIdx.z;
    const int cnt = g_count[s];
    const int m0  = blockIdx.x * 128;
    if (m0 >= cnt) return;
    const int off  = g_offset[s];
    const int rows = min(128, cnt - m0);
    const int n0   = blockIdx.y * BN;
    const int tid  = threadIdx.x;

    const float* in = (LAYER == 0) ? xin : (LAYER == 1 ? g_h1 : g_h2);
    float*      out = (LAYER == 2) ? xout : (LAYER == 0 ? g_h1 : g_h2);

    // ---- A staging (R7 verbatim): 2 float4 per thread per chunk ----
    const int aq = (tid & 3) * 4;                        // float col 0,4,8,12
    const float* aptr[2];
    uint32_t adst[2];
#pragma unroll
    for (int i = 0; i < 2; i++) {
        int r = (tid >> 2) + i * 64;
        int pr = off + m0 + ((r < rows) ? r : 0);        // clamp dead rows
        if (pr > B - 1) pr = B - 1;
        int grow = (LAYER == 0) ? g_perm[pr] : pr;
        aptr[i] = in + (size_t)grow * K + aq;
        adst[i] = (uint32_t)r * ROWB + aq * 2;
    }
    // ---- B staging: packed words, <=1 uint4 per plane per thread ----
    const bool bact = (tid < BU4);
    const uint32_t* bsrcH = nullptr;
    const uint32_t* bsrcL = nullptr;
    uint32_t bdst = 0;
    if (bact) {
        int k2 = tid / (BN / 4);                         // 0..7
        int ncol = (tid % (BN / 4)) * 4;
        size_t wofs = ((size_t)s * (K / 2) + k2) * NF + n0 + ncol;
        bsrcH = SWh + wofs;
        bsrcL = SWl + wofs;
        bdst = (uint32_t)k2 * BROWB + ncol * 4;
    }

    const int lane = tid & 31, w = tid >> 5;
    const int wm = (w >> 2) * 64;                        // 2 warp rows
    const int wn = (w & 3) * (BN / 4);                   // 4 warp cols
    const int g  = lane >> 2, tg = lane & 3;

    float acc[MI][NI][4];
#pragma unroll
    for (int mi = 0; mi < MI; mi++)
#pragma unroll
        for (int ni = 0; ni < NI; ni++)
#pragma unroll
            for (int e = 0; e < 4; e++) acc[mi][ni][e] = 0.f;

    float4 aS[2];
    uint4 bSh, bSl;

    // ---- prologue: stage chunk 0 into buffer 0 ----
#pragma unroll
    for (int i = 0; i < 2; i++) aS[i] = *(const float4*)(aptr[i]);
    if (bact) {
        bSh = *(const uint4*)(bsrcH);
        bSl = *(const uint4*)(bsrcL);
    }
#pragma unroll
    for (int i = 0; i < 2; i++) {
        uint2 hi, lo;
        split4(aS[i], hi, lo);
        *(uint2*)(sm + adst[i])       = hi;
        *(uint2*)(sm + adst[i] + APL) = lo;
    }
    if (bact) {
        *(uint4*)(sm + 2 * APL + bdst)       = bSh;
        *(uint4*)(sm + 2 * APL + bdst + BPL) = bSl;
    }
    __syncthreads();

    for (int c = 0; c < NCH; c++) {
        // prefetch chunk c+1 (global latency overlaps the mma below)
        if (c + 1 < NCH) {
            const int k1 = (c + 1) * 16;
#pragma unroll
            for (int i = 0; i < 2; i++) aS[i] = *(const float4*)(aptr[i] + k1);
            if (bact) {
                const size_t adv = (size_t)(c + 1) * 8 * NF;
                bSh = *(const uint4*)(bsrcH + adv);
                bSl = *(const uint4*)(bsrcL + adv);
            }
        }

        const char* Ab = sm + (c & 1) * BUFSZ;
        const char* Bb = Ab + 2 * APL;

        // A fragments (R7 verbatim): plain lds.32
        uint32_t ah[MI][4], al[MI][4];
#pragma unroll
        for (int mi = 0; mi < MI; mi++) {
            uint32_t base = (uint32_t)(wm + mi * 16 + g) * ROWB + 4 * tg;
            ah[mi][0] = *(const uint32_t*)(Ab + base);
            ah[mi][1] = *(const uint32_t*)(Ab + base + 8 * ROWB);
            ah[mi][2] = *(const uint32_t*)(Ab + base + 16);
            ah[mi][3] = *(const uint32_t*)(Ab + base + 8 * ROWB + 16);
            al[mi][0] = *(const uint32_t*)(Ab + base + APL);
            al[mi][1] = *(const uint32_t*)(Ab + base + APL + 8 * ROWB);
            al[mi][2] = *(const uint32_t*)(Ab + base + APL + 16);
            al[mi][3] = *(const uint32_t*)(Ab + base + APL + 8 * ROWB + 16);
        }
        // B fragments: single lds.32 per register from packed words
        uint32_t bh[NI][2], bl[NI][2];
#pragma unroll
        for (int ni = 0; ni < NI; ni++) {
            uint32_t w0 = (uint32_t)tg * BROWW + wn + ni * 8 + g;
            uint32_t w1 = w0 + 4 * BROWW;
            bh[ni][0] = *(const uint32_t*)(Bb + 4 * w0);
            bh[ni][1] = *(const uint32_t*)(Bb + 4 * w1);
            bl[ni][0] = *(const uint32_t*)(Bb + BPL + 4 * w0);
            bl[ni][1] = *(const uint32_t*)(Bb + BPL + 4 * w1);
        }
#pragma unroll
        for (int mi = 0; mi < MI; mi++)
#pragma unroll
            for (int ni = 0; ni < NI; ni++) {
                MMA_BF16(acc[mi][ni], ah[mi], bh[ni]);
                MMA_BF16(acc[mi][ni], ah[mi], bl[ni]);
                MMA_BF16(acc[mi][ni], al[mi], bh[ni]);
            }

        // store prefetched chunk into the other buffer
        if (c + 1 < NCH) {
            char* D = sm + ((c + 1) & 1) * BUFSZ;
#pragma unroll
            for (int i = 0; i < 2; i++) {
                uint2 hi, lo;
                split4(aS[i], hi, lo);
                *(uint2*)(D + adst[i])       = hi;
                *(uint2*)(D + adst[i] + APL) = lo;
            }
            if (bact) {
                *(uint4*)(D + 2 * APL + bdst)       = bSh;
                *(uint4*)(D + 2 * APL + bdst + BPL) = bSl;
            }
        }
        __syncthreads();
    }

    // ----------------------------- epilogue (R7 verbatim) ------------------
    const float* bs = bias + (size_t)s * NF + n0;
    const float* gb = gbias + n0;
#pragma unroll
    for (int mi = 0; mi < MI; mi++) {
        const int rbase = wm + mi * 16 + g;
#pragma unroll
        for (int ni = 0; ni < NI; ni++) {
            const int c0 = wn + ni * 8 + 2 * tg;
            const float bv0 = bs[c0] + gb[c0];
            const float bv1 = bs[c0 + 1] + gb[c0 + 1];
#pragma unroll
            for (int half = 0; half < 2; half++) {
                const int r = rbase + half * 8;
                if (r < rows) {
                    float v0 = acc[mi][ni][half * 2 + 0] + bv0;
                    float v1 = acc[mi][ni][half * 2 + 1] + bv1;
                    if (RELU) { v0 = fmaxf(v0, 0.f); v1 = fmaxf(v1, 0.f); }
                    const int prow = off + m0 + r;
                    const int orow = (LAYER == 2) ? g_perm[prow] : prow;
                    *(float2*)(out + (size_t)orow * NF + n0 + c0) = make_float2(v0, v1);
                }
            }
        }
    }
}

// ---------------------------------------------------------------------------
extern "C" void kernel_launch(void* const* d_in, const int* in_sizes, int n_in,
                              void* d_out, int out_size) {
    const float* x     = (const float*)d_in[0];
    const int*   scene = (const int*)d_in[1];   // int32 or int64, auto-detected
    const float* W0  = (const float*)d_in[2];
    const float* b0  = (const float*)d_in[3];
    const float* gW0 = (const float*)d_in[4];
    const float* gb0 = (const float*)d_in[5];
    const float* W1  = (const float*)d_in[6];
    const float* b1  = (const float*)d_in[7];
    const float* gW1 = (const float*)d_in[8];
    const float* gb1 = (const float*)d_in[9];
    const float* W2  = (const float*)d_in[10];
    const float* b2  = (const float*)d_in[11];
    const float* gW2 = (const float*)d_in[12];
    const float* gb2 = (const float*)d_in[13];
    float* out = (float*)d_out;

    const int B = in_sizes[1];
    const int mtiles = (B + 127) / 128;

    // smem: L0/L1: 2*(2*6144 + 2*8*136*4) = 46336; L2: 2*(2*6144 + 2*8*72*4) = 33792
    const int SM_L01 = 2 * (2 * 128 * 48 + 2 * 8 * (128 + 8) * 4);
    const int SM_L2  = 2 * (2 * 128 * 48 + 2 * 8 * (64 + 8) * 4);

    k_init<<<1, 32>>>();
    k_count<<<(B + 255) / 256, 256>>>(scene, B);
    k_scan<<<1, 1>>>();
    k_scatter<<<(B + 255) / 256, 256>>>(scene, B);

    k_splitw<D0, D1><<<512, 256>>>(W0, gW0, g_SWh0, g_SWl0);
    k_splitw<D1, D2><<<256, 256>>>(W1, gW1, g_SWh1, g_SWl1);
    k_splitw<D2, D3><<<64, 256>>>(W2, gW2, g_SWh2, g_SWl2);

    k_gemm<0, D0, D1, 128, true ><<<dim3(mtiles, D1 / 128, NS), 256, SM_L01>>>(
        x, nullptr, g_SWh0, g_SWl0, b0, gb0, B);
    k_gemm<1, D1, D2, 128, true ><<<dim3(mtiles, D2 / 128, NS), 256, SM_L01>>>(
        nullptr, nullptr, g_SWh1, g_SWl1, b1, gb1, B);
    k_gemm<2, D2, D3, 64, false><<<dim3(mtiles, 1, NS), 256, SM_L2>>>(
        nullptr, out, g_SWh2, g_SWl2, b2, gb2, B);
}

// round 10
// speedup vs baseline: 5.5841x; 5.5681x over previous
#include <cuda_runtime.h>
#include <cuda_bf16.h>
#include <cstdint>

// ---------------------------------------------------------------------------
// STARDNN on GB300. R10 = R7 VERBATIM (A/A test).
// R8 (512t/K32/packed-B) and R9 (R7-geometry/packed-B) both measured ~1280us,
// within 0.3% of each other, vs R7's 229.6us — despite R9's mainloop being
// strictly cheaper than R7's by instruction count. Resubmitting the proven
// 229.6us source unchanged disambiguates code regression vs environment drift.
// ---------------------------------------------------------------------------

#define NS    7
#define MAXB  16384
#define D0    512
#define D1    512
#define D2    256
#define D3    64

// scratch (allocation-free: __device__ globals) — identical set to R2 (passed)
__device__ int   g_count[NS];
__device__ int   g_offset[NS];
__device__ int   g_cursor[NS];
__device__ int   g_perm[MAXB];
__device__ float g_h1[MAXB * D1];
__device__ float g_h2[MAXB * D2];
__device__ float g_SW0[NS * D0 * D1];
__device__ float g_SW1[NS * D1 * D2];
__device__ float g_SW2[NS * D2 * D3];

// ------------------------------ helpers ------------------------------------
#define MMA_BF16(d, a, b) \
    asm volatile("mma.sync.aligned.m16n8k16.row.col.f32.bf16.bf16.f32 " \
                 "{%0,%1,%2,%3}, {%4,%5,%6,%7}, {%8,%9}, {%0,%1,%2,%3};" \
                 : "+f"((d)[0]), "+f"((d)[1]), "+f"((d)[2]), "+f"((d)[3]) \
                 : "r"((a)[0]), "r"((a)[1]), "r"((a)[2]), "r"((a)[3]), \
                   "r"((b)[0]), "r"((b)[1]))

__device__ __forceinline__ void bsplit(float v, __nv_bfloat16& h, __nv_bfloat16& l) {
    h = __float2bfloat16(v);
    l = __float2bfloat16(v - __bfloat162float(h));
}

__device__ __forceinline__ uint32_t pack2(__nv_bfloat16 a, __nv_bfloat16 b) {
    union { __nv_bfloat16 h[2]; uint32_t u; } t;
    t.h[0] = a; t.h[1] = b;
    return t.u;
}

// split a float4 into hi/lo packed uint2
__device__ __forceinline__ void split4(float4 v, uint2& hi, uint2& lo) {
    __nv_bfloat16 h0, l0, h1, l1, h2, l2, h3, l3;
    bsplit(v.x, h0, l0); bsplit(v.y, h1, l1);
    bsplit(v.z, h2, l2); bsplit(v.w, h3, l3);
    hi.x = pack2(h0, h1); hi.y = pack2(h2, h3);
    lo.x = pack2(l0, l1); lo.y = pack2(l2, l3);
}

// ------------------------------ bucketing (verbatim R2) --------------------
__device__ __forceinline__ int scene_at(const int* __restrict__ p, int b, bool is64) {
    int v = is64 ? p[2 * b] : p[b];
    int s = v - 1;
    return (s < 0) ? 0 : (s >= NS ? NS - 1 : s);
}

__global__ void k_init() {
    if (threadIdx.x < NS) g_count[threadIdx.x] = 0;
}

__global__ void k_count(const int* __restrict__ scene, int B) {
    int b = blockIdx.x * blockDim.x + threadIdx.x;
    if (b < B) {
        bool is64 = (scene[1] == 0);
        atomicAdd(&g_count[scene_at(scene, b, is64)], 1);
    }
}

__global__ void k_scan() {
    int off = 0;
    for (int s = 0; s < NS; s++) {
        g_offset[s] = off;
        g_cursor[s] = off;
        off += g_count[s];
    }
}

__global__ void k_scatter(const int* __restrict__ scene, int B) {
    int b = blockIdx.x * blockDim.x + threadIdx.x;
    if (b < B) {
        bool is64 = (scene[1] == 0);
        int s = scene_at(scene, b, is64);
        int pos = atomicAdd(&g_cursor[s], 1);
        g_perm[pos] = b;
    }
}

// Pre-scale all weights (verbatim R2): SW[s][k][n] = W[s][k][n] * gW[k][n]
__global__ void k_scale_all(const float* __restrict__ W0, const float* __restrict__ gW0,
                            const float* __restrict__ W1, const float* __restrict__ gW1,
                            const float* __restrict__ W2, const float* __restrict__ gW2) {
    int stride = gridDim.x * blockDim.x;
    int t = blockIdx.x * blockDim.x + threadIdx.x;
    for (int j = t; j < D0 * D1; j += stride) {
        float g = gW0[j];
#pragma unroll
        for (int s = 0; s < NS; s++) g_SW0[s * D0 * D1 + j] = W0[s * D0 * D1 + j] * g;
    }
    for (int j = t; j < D1 * D2; j += stride) {
        float g = gW1[j];
#pragma unroll
        for (int s = 0; s < NS; s++) g_SW1[s * D1 * D2 + j] = W1[s * D1 * D2 + j] * g;
    }
    for (int j = t; j < D2 * D3; j += stride) {
        float g = gW2[j];
#pragma unroll
        for (int s = 0; s < NS; s++) g_SW2[s * D2 * D3 + j] = W2[s * D2 * D3 + j] * g;
    }
}

// ------------------------------ mma GEMM -----------------------------------
// CTA: 128 x BN tile of one scene bucket (grid: mtiles x ntiles x NS, early
// return like R2). K in chunks of 16.  In-kernel bf16 hi/lo split at stage.
// A smem: [128][16] bf16 rows, ROWB=48 (32B data + 16B pad) hi/lo planes.
// B smem: [16][BN] bf16 rows, BROWB=BN*2+16, hi/lo planes.
// Fragments via plain 32/16-bit shared loads. 8 warps = 2 x 4 (WM=64, WN=BN/4).
template <int LAYER, int K, int NF, int BN, bool RELU>
__global__ __launch_bounds__(256) void k_gemm(const float* __restrict__ xin,
                                              float* __restrict__ xout,
                                              const float* __restrict__ bias,
                                              const float* __restrict__ gbias,
                                              int B) {
    constexpr int MI = 4;                 // WM=64 -> 4 m16 tiles
    constexpr int NI = BN / 4 / 8;        // WN=BN/4 -> NI n8 tiles
    constexpr int NCH = K / 16;
    constexpr int ROWB = 48;
    constexpr int APL = 128 * ROWB;       // 6144
    constexpr int BROWB = BN * 2 + 16;
    constexpr int BPL = 16 * BROWB;
    constexpr int BUFSZ = 2 * APL + 2 * BPL;
    constexpr int BPT = BN / 64;          // B float4 loads per thread (2 or 1)

    extern __shared__ char sm[];

    const int s   = blockIdx.z;
    const int cnt = g_count[s];
    const int m0  = blockIdx.x * 128;
    if (m0 >= cnt) return;
    const int off  = g_offset[s];
    const int rows = min(128, cnt - m0);
    const int n0   = blockIdx.y * BN;
    const int tid  = threadIdx.x;

    const float* in = (LAYER == 0) ? xin : (LAYER == 1 ? g_h1 : g_h2);
    float*      out = (LAYER == 2) ? xout : (LAYER == 0 ? g_h1 : g_h2);
    const float* SW = (LAYER == 0) ? g_SW0 : (LAYER == 1 ? g_SW1 : g_SW2);

    // ---- per-thread stage descriptors (k0 advances each chunk) ----
    // A: 512 float4 per chunk -> 2 per thread (rows tid>>2 and 64+(tid>>2))
    const int aq = (tid & 3) * 4;                        // float col 0,4,8,12
    const float* aptr[2];
    uint32_t adst[2];
#pragma unroll
    for (int i = 0; i < 2; i++) {
        int r = (tid >> 2) + i * 64;
        int pr = off + m0 + ((r < rows) ? r : 0);        // clamp dead rows
        if (pr > B - 1) pr = B - 1;
        int grow = (LAYER == 0) ? g_perm[pr] : pr;
        aptr[i] = in + (size_t)grow * K + aq;
        adst[i] = (uint32_t)r * ROWB + aq * 2;
    }
    // B: 16*BN/4 float4 per chunk -> BPT per thread
    const float* bptr[BPT];
    uint32_t bdst[BPT];
#pragma unroll
    for (int i = 0; i < BPT; i++) {
        int j = tid + i * 256;
        int krow = j / (BN / 4);
        int ncol = (j % (BN / 4)) * 4;
        bptr[i] = SW + ((size_t)s * K + krow) * NF + n0 + ncol;
        bdst[i] = (uint32_t)krow * BROWB + ncol * 2;
    }

    const int lane = tid & 31, w = tid >> 5;
    const int wm = (w >> 2) * 64;                        // 2 warp rows
    const int wn = (w & 3) * (BN / 4);                   // 4 warp cols
    const int g  = lane >> 2, tg = lane & 3;

    float acc[MI][NI][4];
#pragma unroll
    for (int mi = 0; mi < MI; mi++)
#pragma unroll
        for (int ni = 0; ni < NI; ni++)
#pragma unroll
            for (int e = 0; e < 4; e++) acc[mi][ni][e] = 0.f;

    float4 aS[2], bS[BPT];

    // ---- prologue: stage chunk 0 into buffer 0 ----
#pragma unroll
    for (int i = 0; i < 2; i++) aS[i] = *(const float4*)(aptr[i]);
#pragma unroll
    for (int i = 0; i < BPT; i++) bS[i] = *(const float4*)(bptr[i]);
#pragma unroll
    for (int i = 0; i < 2; i++) {
        uint2 hi, lo;
        split4(aS[i], hi, lo);
        *(uint2*)(sm + adst[i])       = hi;
        *(uint2*)(sm + adst[i] + APL) = lo;
    }
#pragma unroll
    for (int i = 0; i < BPT; i++) {
        uint2 hi, lo;
        split4(bS[i], hi, lo);
        *(uint2*)(sm + 2 * APL + bdst[i])       = hi;
        *(uint2*)(sm + 2 * APL + bdst[i] + BPL) = lo;
    }
    __syncthreads();

    for (int c = 0; c < NCH; c++) {
        // prefetch chunk c+1 (global latency overlaps the mma below)
        if (c + 1 < NCH) {
            const int k1 = (c + 1) * 16;
#pragma unroll
            for (int i = 0; i < 2; i++) aS[i] = *(const float4*)(aptr[i] + k1);
#pragma unroll
            for (int i = 0; i < BPT; i++) bS[i] = *(const float4*)(bptr[i] + (size_t)k1 * NF);
        }

        const char* Ab = sm + (c & 1) * BUFSZ;
        const char* Bb = Ab + 2 * APL;

        // A fragments (hi and lo planes): plain lds.32
        uint32_t ah[MI][4], al[MI][4];
#pragma unroll
        for (int mi = 0; mi < MI; mi++) {
            uint32_t base = (uint32_t)(wm + mi * 16 + g) * ROWB + 4 * tg;
            ah[mi][0] = *(const uint32_t*)(Ab + base);
            ah[mi][1] = *(const uint32_t*)(Ab + base + 8 * ROWB);
            ah[mi][2] = *(const uint32_t*)(Ab + base + 16);
            ah[mi][3] = *(const uint32_t*)(Ab + base + 8 * ROWB + 16);
            al[mi][0] = *(const uint32_t*)(Ab + base + APL);
            al[mi][1] = *(const uint32_t*)(Ab + base + APL + 8 * ROWB);
            al[mi][2] = *(const uint32_t*)(Ab + base + APL + 16);
            al[mi][3] = *(const uint32_t*)(Ab + base + APL + 8 * ROWB + 16);
        }
        // B fragments: pairs of 16-bit loads (k rows, n cols)
        uint32_t bh[NI][2], bl[NI][2];
#pragma unroll
        for (int ni = 0; ni < NI; ni++) {
            uint32_t cb = 2u * (wn + ni * 8 + g);
#pragma unroll
            for (int pl = 0; pl < 2; pl++) {
                const char* P = Bb + pl * BPL + cb;
                uint32_t x0 = *(const unsigned short*)(P + (2 * tg) * BROWB);
                uint32_t x1 = *(const unsigned short*)(P + (2 * tg + 1) * BROWB);
                uint32_t x2 = *(const unsigned short*)(P + (2 * tg + 8) * BROWB);
                uint32_t x3 = *(const unsigned short*)(P + (2 * tg + 9) * BROWB);
                if (pl == 0) { bh[ni][0] = x0 | (x1 << 16); bh[ni][1] = x2 | (x3 << 16); }
                else         { bl[ni][0] = x0 | (x1 << 16); bl[ni][1] = x2 | (x3 << 16); }
            }
        }
#pragma unroll
        for (int mi = 0; mi < MI; mi++)
#pragma unroll
            for (int ni = 0; ni < NI; ni++) {
                MMA_BF16(acc[mi][ni], ah[mi], bh[ni]);
                MMA_BF16(acc[mi][ni], ah[mi], bl[ni]);
                MMA_BF16(acc[mi][ni], al[mi], bh[ni]);
            }

        // store prefetched chunk into the other buffer
        if (c + 1 < NCH) {
            char* D = sm + ((c + 1) & 1) * BUFSZ;
#pragma unroll
            for (int i = 0; i < 2; i++) {
                uint2 hi, lo;
                split4(aS[i], hi, lo);
                *(uint2*)(D + adst[i])       = hi;
                *(uint2*)(D + adst[i] + APL) = lo;
            }
#pragma unroll
            for (int i = 0; i < BPT; i++) {
                uint2 hi, lo;
                split4(bS[i], hi, lo);
                *(uint2*)(D + 2 * APL + bdst[i])       = hi;
                *(uint2*)(D + 2 * APL + bdst[i] + BPL) = lo;
            }
        }
        __syncthreads();
    }

    // ----------------------------- epilogue --------------------------------
    const float* bs = bias + (size_t)s * NF + n0;
    const float* gb = gbias + n0;
#pragma unroll
    for (int mi = 0; mi < MI; mi++) {
        const int rbase = wm + mi * 16 + g;
#pragma unroll
        for (int ni = 0; ni < NI; ni++) {
            const int c0 = wn + ni * 8 + 2 * tg;
            const float bv0 = bs[c0] + gb[c0];
            const float bv1 = bs[c0 + 1] + gb[c0 + 1];
#pragma unroll
            for (int half = 0; half < 2; half++) {
                const int r = rbase + half * 8;
                if (r < rows) {
                    float v0 = acc[mi][ni][half * 2 + 0] + bv0;
                    float v1 = acc[mi][ni][half * 2 + 1] + bv1;
                    if (RELU) { v0 = fmaxf(v0, 0.f); v1 = fmaxf(v1, 0.f); }
                    const int prow = off + m0 + r;
                    const int orow = (LAYER == 2) ? g_perm[prow] : prow;
                    *(float2*)(out + (size_t)orow * NF + n0 + c0) = make_float2(v0, v1);
                }
            }
        }
    }
}

// ---------------------------------------------------------------------------
extern "C" void kernel_launch(void* const* d_in, const int* in_sizes, int n_in,
                              void* d_out, int out_size) {
    const float* x     = (const float*)d_in[0];
    const int*   scene = (const int*)d_in[1];   // int32 or int64, auto-detected
    const float* W0  = (const float*)d_in[2];
    const float* b0  = (const float*)d_in[3];
    const float* gW0 = (const float*)d_in[4];
    const float* gb0 = (const float*)d_in[5];
    const float* W1  = (const float*)d_in[6];
    const float* b1  = (const float*)d_in[7];
    const float* gW1 = (const float*)d_in[8];
    const float* gb1 = (const float*)d_in[9];
    const float* W2  = (const float*)d_in[10];
    const float* b2  = (const float*)d_in[11];
    const float* gW2 = (const float*)d_in[12];
    const float* gb2 = (const float*)d_in[13];
    float* out = (float*)d_out;

    const int B = in_sizes[1];
    const int mtiles = (B + 127) / 128;

    // smem: L0/L1: 2*(2*6144 + 2*16*272) = 41984; L2: 2*(2*6144 + 2*16*144) = 33792
    const int SM_L01 = 2 * (2 * 128 * 48 + 2 * 16 * (128 * 2 + 16));
    const int SM_L2  = 2 * (2 * 128 * 48 + 2 * 16 * (64 * 2 + 16));

    k_init<<<1, 32>>>();
    k_count<<<(B + 255) / 256, 256>>>(scene, B);
    k_scan<<<1, 1>>>();
    k_scatter<<<(B + 255) / 256, 256>>>(scene, B);
    k_scale_all<<<1024, 256>>>(W0, gW0, W1, gW1, W2, gW2);

    k_gemm<0, D0, D1, 128, true ><<<dim3(mtiles, D1 / 128, NS), 256, SM_L01>>>(
        x, nullptr, b0, gb0, B);
    k_gemm<1, D1, D2, 128, true ><<<dim3(mtiles, D2 / 128, NS), 256, SM_L01>>>(
        nullptr, nullptr, b1, gb1, B);
    k_gemm<2, D2, D3, 64, false><<<dim3(mtiles, 1, NS), 256, SM_L2>>>(
        nullptr, out, b2, gb2, B);
}

// round 11
// speedup vs baseline: 5.7942x; 1.0376x over previous
#include <cuda_runtime.h>
#include <cuda_bf16.h>
#include <cstdint>

// ---------------------------------------------------------------------------
// STARDNN on GB300. R11 = R7/R10 (229.5us proven) + two scoped changes:
//  (1) B smem staged in k-pair packed uint32 words -> B fragments are single
//      lds.32 (replaces 32 lds.16 + 16 LOP per thread per chunk).
//      Weights remain fp32 in gmem via k_scale_all (the R8/R9 gmem pre-pack
//      path is quarantined).
//  (2) Layer-2 GEMM uses BM=64 tiles (live CTAs 133 -> ~266, better hiding).
// ---------------------------------------------------------------------------

#define NS    7
#define MAXB  16384
#define D0    512
#define D1    512
#define D2    256
#define D3    64

// scratch (allocation-free: __device__ globals)
__device__ int   g_count[NS];
__device__ int   g_offset[NS];
__device__ int   g_cursor[NS];
__device__ int   g_perm[MAXB];
__device__ float g_h1[MAXB * D1];
__device__ float g_h2[MAXB * D2];
__device__ float g_SW0[NS * D0 * D1];
__device__ float g_SW1[NS * D1 * D2];
__device__ float g_SW2[NS * D2 * D3];

// ------------------------------ helpers ------------------------------------
#define MMA_BF16(d, a, b) \
    asm volatile("mma.sync.aligned.m16n8k16.row.col.f32.bf16.bf16.f32 " \
                 "{%0,%1,%2,%3}, {%4,%5,%6,%7}, {%8,%9}, {%0,%1,%2,%3};" \
                 : "+f"((d)[0]), "+f"((d)[1]), "+f"((d)[2]), "+f"((d)[3]) \
                 : "r"((a)[0]), "r"((a)[1]), "r"((a)[2]), "r"((a)[3]), \
                   "r"((b)[0]), "r"((b)[1]))

__device__ __forceinline__ void bsplit(float v, __nv_bfloat16& h, __nv_bfloat16& l) {
    h = __float2bfloat16(v);
    l = __float2bfloat16(v - __bfloat162float(h));
}

__device__ __forceinline__ uint32_t pack2(__nv_bfloat16 a, __nv_bfloat16 b) {
    union { __nv_bfloat16 h[2]; uint32_t u; } t;
    t.h[0] = a; t.h[1] = b;
    return t.u;
}

// split a float4 into hi/lo packed uint2 (n-adjacent pairs; for A staging)
__device__ __forceinline__ void split4(float4 v, uint2& hi, uint2& lo) {
    __nv_bfloat16 h0, l0, h1, l1, h2, l2, h3, l3;
    bsplit(v.x, h0, l0); bsplit(v.y, h1, l1);
    bsplit(v.z, h2, l2); bsplit(v.w, h3, l3);
    hi.x = pack2(h0, h1); hi.y = pack2(h2, h3);
    lo.x = pack2(l0, l1); lo.y = pack2(l2, l3);
}

// pack two k-adjacent rows (same 4 n's) into k-pair words (for B staging)
__device__ __forceinline__ void packk4(float4 f0, float4 f1, uint4& hi, uint4& lo) {
    __nv_bfloat16 h0a, l0a, h0b, l0b;
    bsplit(f0.x, h0a, l0a); bsplit(f1.x, h0b, l0b);
    hi.x = pack2(h0a, h0b); lo.x = pack2(l0a, l0b);
    bsplit(f0.y, h0a, l0a); bsplit(f1.y, h0b, l0b);
    hi.y = pack2(h0a, h0b); lo.y = pack2(l0a, l0b);
    bsplit(f0.z, h0a, l0a); bsplit(f1.z, h0b, l0b);
    hi.z = pack2(h0a, h0b); lo.z = pack2(l0a, l0b);
    bsplit(f0.w, h0a, l0a); bsplit(f1.w, h0b, l0b);
    hi.w = pack2(h0a, h0b); lo.w = pack2(l0a, l0b);
}

// ------------------------------ bucketing (proven) -------------------------
__device__ __forceinline__ int scene_at(const int* __restrict__ p, int b, bool is64) {
    int v = is64 ? p[2 * b] : p[b];
    int s = v - 1;
    return (s < 0) ? 0 : (s >= NS ? NS - 1 : s);
}

__global__ void k_init() {
    if (threadIdx.x < NS) g_count[threadIdx.x] = 0;
}

__global__ void k_count(const int* __restrict__ scene, int B) {
    int b = blockIdx.x * blockDim.x + threadIdx.x;
    if (b < B) {
        bool is64 = (scene[1] == 0);
        atomicAdd(&g_count[scene_at(scene, b, is64)], 1);
    }
}

__global__ void k_scan() {
    int off = 0;
    for (int s = 0; s < NS; s++) {
        g_offset[s] = off;
        g_cursor[s] = off;
        off += g_count[s];
    }
}

__global__ void k_scatter(const int* __restrict__ scene, int B) {
    int b = blockIdx.x * blockDim.x + threadIdx.x;
    if (b < B) {
        bool is64 = (scene[1] == 0);
        int s = scene_at(scene, b, is64);
        int pos = atomicAdd(&g_cursor[s], 1);
        g_perm[pos] = b;
    }
}

// Pre-scale all weights (proven): SW[s][k][n] = W[s][k][n] * gW[k][n]
__global__ void k_scale_all(const float* __restrict__ W0, const float* __restrict__ gW0,
                            const float* __restrict__ W1, const float* __restrict__ gW1,
                            const float* __restrict__ W2, const float* __restrict__ gW2) {
    int stride = gridDim.x * blockDim.x;
    int t = blockIdx.x * blockDim.x + threadIdx.x;
    for (int j = t; j < D0 * D1; j += stride) {
        float g = gW0[j];
#pragma unroll
        for (int s = 0; s < NS; s++) g_SW0[s * D0 * D1 + j] = W0[s * D0 * D1 + j] * g;
    }
    for (int j = t; j < D1 * D2; j += stride) {
        float g = gW1[j];
#pragma unroll
        for (int s = 0; s < NS; s++) g_SW1[s * D1 * D2 + j] = W1[s * D1 * D2 + j] * g;
    }
    for (int j = t; j < D2 * D3; j += stride) {
        float g = gW2[j];
#pragma unroll
        for (int s = 0; s < NS; s++) g_SW2[s * D2 * D3 + j] = W2[s * D2 * D3 + j] * g;
    }
}

// ------------------------------ mma GEMM -----------------------------------
// CTA: BM x BN tile of one scene bucket.  K in chunks of 16, register-staged
// double buffer (proven).  A smem: [BM][16] bf16 rows, ROWB=48, hi/lo planes.
// B smem: k-pair packed words [8][BN+8] per plane; fragment regs = single
// lds.32 at word tg*(BN+8)+col (banks 8tg+g: conflict-free).
// 8 warps: (BM/64)x... warp grid 2x4 for BM=128 (WM=64), 2x4 WM=32 for BM=64.
template <int LAYER, int K, int NF, int BM, int BN, bool RELU>
__global__ __launch_bounds__(256) void k_gemm(const float* __restrict__ xin,
                                              float* __restrict__ xout,
                                              const float* __restrict__ bias,
                                              const float* __restrict__ gbias,
                                              int B) {
    constexpr int MI = BM / 2 / 16;       // m16 tiles per warp (4 or 2)
    constexpr int NI = BN / 4 / 8;        // n8 tiles per warp
    constexpr int NCH = K / 16;
    constexpr int ROWB = 48;
    constexpr int APL = BM * ROWB;
    constexpr int BROWW = BN + 8;         // words; == 8 mod 32
    constexpr int BROWB = BROWW * 4;
    constexpr int BPLP = 8 * BROWB;       // one B plane (8 k-pair rows)
    constexpr int BUFSZ = 2 * APL + 2 * BPLP;
    constexpr int APT = BM / 64;          // A float4 loads per thread (2 or 1)
    constexpr int BSLOTS = 8 * (BN / 4);  // B (k2, nquad) slots per chunk

    extern __shared__ char sm[];

    const int s   = blockIdx.z;
    const int cnt = g_count[s];
    const int m0  = blockIdx.x * BM;
    if (m0 >= cnt) return;
    const int off  = g_offset[s];
    const int rows = min(BM, cnt - m0);
    const int n0   = blockIdx.y * BN;
    const int tid  = threadIdx.x;

    const float* in = (LAYER == 0) ? xin : (LAYER == 1 ? g_h1 : g_h2);
    float*      out = (LAYER == 2) ? xout : (LAYER == 0 ? g_h1 : g_h2);
    const float* SW = (LAYER == 0) ? g_SW0 : (LAYER == 1 ? g_SW1 : g_SW2);

    // ---- A staging (proven): APT float4 per thread per chunk ----
    const int aq = (tid & 3) * 4;                        // float col 0,4,8,12
    const float* aptr[APT];
    uint32_t adst[APT];
#pragma unroll
    for (int i = 0; i < APT; i++) {
        int r = (tid >> 2) + i * 64;
        int pr = off + m0 + ((r < rows) ? r : 0);        // clamp dead rows
        if (pr > B - 1) pr = B - 1;
        int grow = (LAYER == 0) ? g_perm[pr] : pr;
        aptr[i] = in + (size_t)grow * K + aq;
        adst[i] = (uint32_t)r * ROWB + aq * 2;
    }
    // ---- B staging: one (k-pair, n-quad) slot per active thread ----
    const bool bact = (tid < BSLOTS);
    const float* bptr0 = nullptr;                        // k row 2*k2
    uint32_t bdst = 0;
    if (bact) {
        int k2 = tid / (BN / 4);                         // 0..7
        int ncol = (tid % (BN / 4)) * 4;
        bptr0 = SW + ((size_t)s * K + 2 * k2) * NF + n0 + ncol;
        bdst = (uint32_t)k2 * BROWB + ncol * 4;          // byte offset in plane
    }

    const int lane = tid & 31, w = tid >> 5;
    const int wm = (w >> 2) * (BM / 2);                  // 2 warp rows
    const int wn = (w & 3) * (BN / 4);                   // 4 warp cols
    const int g  = lane >> 2, tg = lane & 3;

    float acc[MI][NI][4];
#pragma unroll
    for (int mi = 0; mi < MI; mi++)
#pragma unroll
        for (int ni = 0; ni < NI; ni++)
#pragma unroll
            for (int e = 0; e < 4; e++) acc[mi][ni][e] = 0.f;

    float4 aS[APT], bF0, bF1;

    // ---- prologue: stage chunk 0 into buffer 0 ----
#pragma unroll
    for (int i = 0; i < APT; i++) aS[i] = *(const float4*)(aptr[i]);
    if (bact) {
        bF0 = *(const float4*)(bptr0);
        bF1 = *(const float4*)(bptr0 + NF);
    }
#pragma unroll
    for (int i = 0; i < APT; i++) {
        uint2 hi, lo;
        split4(aS[i], hi, lo);
        *(uint2*)(sm + adst[i])       = hi;
        *(uint2*)(sm + adst[i] + APL) = lo;
    }
    if (bact) {
        uint4 hi, lo;
        packk4(bF0, bF1, hi, lo);
        *(uint4*)(sm + 2 * APL + bdst)        = hi;
        *(uint4*)(sm + 2 * APL + bdst + BPLP) = lo;
    }
    __syncthreads();

    for (int c = 0; c < NCH; c++) {
        // prefetch chunk c+1 (global latency overlaps the mma below)
        if (c + 1 < NCH) {
            const int k1 = (c + 1) * 16;
#pragma unroll
            for (int i = 0; i < APT; i++) aS[i] = *(const float4*)(aptr[i] + k1);
            if (bact) {
                const float* p = bptr0 + (size_t)k1 * NF;
                bF0 = *(const float4*)(p);
                bF1 = *(const float4*)(p + NF);
            }
        }

        const char* Ab = sm + (c & 1) * BUFSZ;
        const char* Bb = Ab + 2 * APL;

        // A fragments (proven): plain lds.32
        uint32_t ah[MI][4], al[MI][4];
#pragma unroll
        for (int mi = 0; mi < MI; mi++) {
            uint32_t base = (uint32_t)(wm + mi * 16 + g) * ROWB + 4 * tg;
            ah[mi][0] = *(const uint32_t*)(Ab + base);
            ah[mi][1] = *(const uint32_t*)(Ab + base + 8 * ROWB);
            ah[mi][2] = *(const uint32_t*)(Ab + base + 16);
            ah[mi][3] = *(const uint32_t*)(Ab + base + 8 * ROWB + 16);
            al[mi][0] = *(const uint32_t*)(Ab + base + APL);
            al[mi][1] = *(const uint32_t*)(Ab + base + APL + 8 * ROWB);
            al[mi][2] = *(const uint32_t*)(Ab + base + APL + 16);
            al[mi][3] = *(const uint32_t*)(Ab + base + APL + 8 * ROWB + 16);
        }
        // B fragments: single lds.32 per register from k-pair packed words
        uint32_t bh[NI][2], bl[NI][2];
#pragma unroll
        for (int ni = 0; ni < NI; ni++) {
            uint32_t w0 = (uint32_t)tg * BROWW + wn + ni * 8 + g;
            uint32_t w1 = w0 + 4 * BROWW;
            bh[ni][0] = *(const uint32_t*)(Bb + 4 * w0);
            bh[ni][1] = *(const uint32_t*)(Bb + 4 * w1);
            bl[ni][0] = *(const uint32_t*)(Bb + BPLP + 4 * w0);
            bl[ni][1] = *(const uint32_t*)(Bb + BPLP + 4 * w1);
        }
#pragma unroll
        for (int mi = 0; mi < MI; mi++)
#pragma unroll
            for (int ni = 0; ni < NI; ni++) {
                MMA_BF16(acc[mi][ni], ah[mi], bh[ni]);
                MMA_BF16(acc[mi][ni], ah[mi], bl[ni]);
                MMA_BF16(acc[mi][ni], al[mi], bh[ni]);
            }

        // store prefetched chunk into the other buffer
        if (c + 1 < NCH) {
            char* D = sm + ((c + 1) & 1) * BUFSZ;
#pragma unroll
            for (int i = 0; i < APT; i++) {
                uint2 hi, lo;
                split4(aS[i], hi, lo);
                *(uint2*)(D + adst[i])       = hi;
                *(uint2*)(D + adst[i] + APL) = lo;
            }
            if (bact) {
                uint4 hi, lo;
                packk4(bF0, bF1, hi, lo);
                *(uint4*)(D + 2 * APL + bdst)        = hi;
                *(uint4*)(D + 2 * APL + bdst + BPLP) = lo;
            }
        }
        __syncthreads();
    }

    // ----------------------------- epilogue (proven) -----------------------
    const float* bs = bias + (size_t)s * NF + n0;
    const float* gb = gbias + n0;
#pragma unroll
    for (int mi = 0; mi < MI; mi++) {
        const int rbase = wm + mi * 16 + g;
#pragma unroll
        for (int ni = 0; ni < NI; ni++) {
            const int c0 = wn + ni * 8 + 2 * tg;
            const float bv0 = bs[c0] + gb[c0];
            const float bv1 = bs[c0 + 1] + gb[c0 + 1];
#pragma unroll
            for (int half = 0; half < 2; half++) {
                const int r = rbase + half * 8;
                if (r < rows) {
                    float v0 = acc[mi][ni][half * 2 + 0] + bv0;
                    float v1 = acc[mi][ni][half * 2 + 1] + bv1;
                    if (RELU) { v0 = fmaxf(v0, 0.f); v1 = fmaxf(v1, 0.f); }
                    const int prow = off + m0 + r;
                    const int orow = (LAYER == 2) ? g_perm[prow] : prow;
                    *(float2*)(out + (size_t)orow * NF + n0 + c0) = make_float2(v0, v1);
                }
            }
        }
    }
}

// ---------------------------------------------------------------------------
extern "C" void kernel_launch(void* const* d_in, const int* in_sizes, int n_in,
                              void* d_out, int out_size) {
    const float* x     = (const float*)d_in[0];
    const int*   scene = (const int*)d_in[1];   // int32 or int64, auto-detected
    const float* W0  = (const float*)d_in[2];
    const float* b0  = (const float*)d_in[3];
    const float* gW0 = (const float*)d_in[4];
    const float* gb0 = (const float*)d_in[5];
    const float* W1  = (const float*)d_in[6];
    const float* b1  = (const float*)d_in[7];
    const float* gW1 = (const float*)d_in[8];
    const float* gb1 = (const float*)d_in[9];
    const float* W2  = (const float*)d_in[10];
    const float* b2  = (const float*)d_in[11];
    const float* gW2 = (const float*)d_in[12];
    const float* gb2 = (const float*)d_in[13];
    float* out = (float*)d_out;

    const int B = in_sizes[1];
    const int mt128 = (B + 127) / 128;
    const int mt64  = (B + 63) / 64;

    // smem: L0/L1: 2*(2*128*48 + 2*8*(128+8)*4) = 41984 (<48K, no opt-in)
    //       L2:    2*(2*64*48  + 2*8*(64+8)*4)  = 21504
    const int SM_L01 = 2 * (2 * 128 * 48 + 2 * 8 * (128 + 8) * 4);
    const int SM_L2  = 2 * (2 * 64 * 48 + 2 * 8 * (64 + 8) * 4);

    k_init<<<1, 32>>>();
    k_count<<<(B + 255) / 256, 256>>>(scene, B);
    k_scan<<<1, 1>>>();
    k_scatter<<<(B + 255) / 256, 256>>>(scene, B);
    k_scale_all<<<1024, 256>>>(W0, gW0, W1, gW1, W2, gW2);

    k_gemm<0, D0, D1, 128, 128, true ><<<dim3(mt128, D1 / 128, NS), 256, SM_L01>>>(
        x, nullptr, b0, gb0, B);
    k_gemm<1, D1, D2, 128, 128, true ><<<dim3(mt128, D2 / 128, NS), 256, SM_L01>>>(
        nullptr, nullptr, b1, gb1, B);
    k_gemm<2, D2, D3, 64, 64, false><<<dim3(mt64, 1, NS), 256, SM_L2>>>(
        nullptr, out, b2, gb2, B);
}

// round 12
// speedup vs baseline: 6.8342x; 1.1795x over previous
#include <cuda_runtime.h>
#include <cuda_bf16.h>
#include <cstdint>

// ---------------------------------------------------------------------------
// STARDNN on GB300. R12 = R11 (221.2us proven) + ONE change:
// occupancy push to 2 CTAs/SM via __launch_bounds__(256,2) + A-fragment
// register reuse (hi MMAs, then reload same regs with lo).  Arithmetic is
// bit-identical (per-acc order h*h -> h*l -> l*h preserved).
// ---------------------------------------------------------------------------

#define NS    7
#define MAXB  16384
#define D0    512
#define D1    512
#define D2    256
#define D3    64

// scratch (allocation-free: __device__ globals)
__device__ int   g_count[NS];
__device__ int   g_offset[NS];
__device__ int   g_cursor[NS];
__device__ int   g_perm[MAXB];
__device__ float g_h1[MAXB * D1];
__device__ float g_h2[MAXB * D2];
__device__ float g_SW0[NS * D0 * D1];
__device__ float g_SW1[NS * D1 * D2];
__device__ float g_SW2[NS * D2 * D3];

// ------------------------------ helpers ------------------------------------
#define MMA_BF16(d, a, b) \
    asm volatile("mma.sync.aligned.m16n8k16.row.col.f32.bf16.bf16.f32 " \
                 "{%0,%1,%2,%3}, {%4,%5,%6,%7}, {%8,%9}, {%0,%1,%2,%3};" \
                 : "+f"((d)[0]), "+f"((d)[1]), "+f"((d)[2]), "+f"((d)[3]) \
                 : "r"((a)[0]), "r"((a)[1]), "r"((a)[2]), "r"((a)[3]), \
                   "r"((b)[0]), "r"((b)[1]))

__device__ __forceinline__ void bsplit(float v, __nv_bfloat16& h, __nv_bfloat16& l) {
    h = __float2bfloat16(v);
    l = __float2bfloat16(v - __bfloat162float(h));
}

__device__ __forceinline__ uint32_t pack2(__nv_bfloat16 a, __nv_bfloat16 b) {
    union { __nv_bfloat16 h[2]; uint32_t u; } t;
    t.h[0] = a; t.h[1] = b;
    return t.u;
}

// split a float4 into hi/lo packed uint2 (n-adjacent pairs; for A staging)
__device__ __forceinline__ void split4(float4 v, uint2& hi, uint2& lo) {
    __nv_bfloat16 h0, l0, h1, l1, h2, l2, h3, l3;
    bsplit(v.x, h0, l0); bsplit(v.y, h1, l1);
    bsplit(v.z, h2, l2); bsplit(v.w, h3, l3);
    hi.x = pack2(h0, h1); hi.y = pack2(h2, h3);
    lo.x = pack2(l0, l1); lo.y = pack2(l2, l3);
}

// pack two k-adjacent rows (same 4 n's) into k-pair words (for B staging)
__device__ __forceinline__ void packk4(float4 f0, float4 f1, uint4& hi, uint4& lo) {
    __nv_bfloat16 ha, la, hb, lb;
    bsplit(f0.x, ha, la); bsplit(f1.x, hb, lb);
    hi.x = pack2(ha, hb); lo.x = pack2(la, lb);
    bsplit(f0.y, ha, la); bsplit(f1.y, hb, lb);
    hi.y = pack2(ha, hb); lo.y = pack2(la, lb);
    bsplit(f0.z, ha, la); bsplit(f1.z, hb, lb);
    hi.z = pack2(ha, hb); lo.z = pack2(la, lb);
    bsplit(f0.w, ha, la); bsplit(f1.w, hb, lb);
    hi.w = pack2(ha, hb); lo.w = pack2(la, lb);
}

// ------------------------------ bucketing (proven) -------------------------
__device__ __forceinline__ int scene_at(const int* __restrict__ p, int b, bool is64) {
    int v = is64 ? p[2 * b] : p[b];
    int s = v - 1;
    return (s < 0) ? 0 : (s >= NS ? NS - 1 : s);
}

__global__ void k_init() {
    if (threadIdx.x < NS) g_count[threadIdx.x] = 0;
}

__global__ void k_count(const int* __restrict__ scene, int B) {
    int b = blockIdx.x * blockDim.x + threadIdx.x;
    if (b < B) {
        bool is64 = (scene[1] == 0);
        atomicAdd(&g_count[scene_at(scene, b, is64)], 1);
    }
}

__global__ void k_scan() {
    int off = 0;
    for (int s = 0; s < NS; s++) {
        g_offset[s] = off;
        g_cursor[s] = off;
        off += g_count[s];
    }
}

__global__ void k_scatter(const int* __restrict__ scene, int B) {
    int b = blockIdx.x * blockDim.x + threadIdx.x;
    if (b < B) {
        bool is64 = (scene[1] == 0);
        int s = scene_at(scene, b, is64);
        int pos = atomicAdd(&g_cursor[s], 1);
        g_perm[pos] = b;
    }
}

// Pre-scale all weights (proven): SW[s][k][n] = W[s][k][n] * gW[k][n]
__global__ void k_scale_all(const float* __restrict__ W0, const float* __restrict__ gW0,
                            const float* __restrict__ W1, const float* __restrict__ gW1,
                            const float* __restrict__ W2, const float* __restrict__ gW2) {
    int stride = gridDim.x * blockDim.x;
    int t = blockIdx.x * blockDim.x + threadIdx.x;
    for (int j = t; j < D0 * D1; j += stride) {
        float g = gW0[j];
#pragma unroll
        for (int s = 0; s < NS; s++) g_SW0[s * D0 * D1 + j] = W0[s * D0 * D1 + j] * g;
    }
    for (int j = t; j < D1 * D2; j += stride) {
        float g = gW1[j];
#pragma unroll
        for (int s = 0; s < NS; s++) g_SW1[s * D1 * D2 + j] = W1[s * D1 * D2 + j] * g;
    }
    for (int j = t; j < D2 * D3; j += stride) {
        float g = gW2[j];
#pragma unroll
        for (int s = 0; s < NS; s++) g_SW2[s * D2 * D3 + j] = W2[s * D2 * D3 + j] * g;
    }
}

// ------------------------------ mma GEMM -----------------------------------
// CTA: BM x BN tile of one scene bucket.  K in chunks of 16, register-staged
// double buffer (proven).  A smem: [BM][16] bf16 rows, ROWB=48, hi/lo planes.
// B smem: k-pair packed words [8][BN+8] per plane; fragments = single lds.32.
// R12: A fragments loaded hi-first, MMA'd, then the SAME registers reloaded
// with lo (halves A-frag liveness); 2 CTAs/SM forced via __launch_bounds__.
template <int LAYER, int K, int NF, int BM, int BN, bool RELU>
__global__ __launch_bounds__(256, 2) void k_gemm(const float* __restrict__ xin,
                                                 float* __restrict__ xout,
                                                 const float* __restrict__ bias,
                                                 const float* __restrict__ gbias,
                                                 int B) {
    constexpr int MI = BM / 2 / 16;       // m16 tiles per warp (4 or 2)
    constexpr int NI = BN / 4 / 8;        // n8 tiles per warp
    constexpr int NCH = K / 16;
    constexpr int ROWB = 48;
    constexpr int APL = BM * ROWB;
    constexpr int BROWW = BN + 8;         // words; == 8 mod 32
    constexpr int BROWB = BROWW * 4;
    constexpr int BPLP = 8 * BROWB;       // one B plane (8 k-pair rows)
    constexpr int BUFSZ = 2 * APL + 2 * BPLP;
    constexpr int APT = BM / 64;          // A float4 loads per thread (2 or 1)
    constexpr int BSLOTS = 8 * (BN / 4);  // B (k2, nquad) slots per chunk

    extern __shared__ char sm[];

    const int s   = blockIdx.z;
    const int cnt = g_count[s];
    const int m0  = blockIdx.x * BM;
    if (m0 >= cnt) return;
    const int off  = g_offset[s];
    const int rows = min(BM, cnt - m0);
    const int n0   = blockIdx.y * BN;
    const int tid  = threadIdx.x;

    const float* in = (LAYER == 0) ? xin : (LAYER == 1 ? g_h1 : g_h2);
    float*      out = (LAYER == 2) ? xout : (LAYER == 0 ? g_h1 : g_h2);
    const float* SW = (LAYER == 0) ? g_SW0 : (LAYER == 1 ? g_SW1 : g_SW2);

    // ---- A staging (proven): APT float4 per thread per chunk ----
    const int aq = (tid & 3) * 4;                        // float col 0,4,8,12
    const float* aptr[APT];
    uint32_t adst[APT];
#pragma unroll
    for (int i = 0; i < APT; i++) {
        int r = (tid >> 2) + i * 64;
        int pr = off + m0 + ((r < rows) ? r : 0);        // clamp dead rows
        if (pr > B - 1) pr = B - 1;
        int grow = (LAYER == 0) ? g_perm[pr] : pr;
        aptr[i] = in + (size_t)grow * K + aq;
        adst[i] = (uint32_t)r * ROWB + aq * 2;
    }
    // ---- B staging: one (k-pair, n-quad) slot per active thread ----
    const bool bact = (tid < BSLOTS);
    const float* bptr0 = nullptr;                        // k row 2*k2
    uint32_t bdst = 0;
    if (bact) {
        int k2 = tid / (BN / 4);                         // 0..7
        int ncol = (tid % (BN / 4)) * 4;
        bptr0 = SW + ((size_t)s * K + 2 * k2) * NF + n0 + ncol;
        bdst = (uint32_t)k2 * BROWB + ncol * 4;          // byte offset in plane
    }

    const int lane = tid & 31, w = tid >> 5;
    const int wm = (w >> 2) * (BM / 2);                  // 2 warp rows
    const int wn = (w & 3) * (BN / 4);                   // 4 warp cols
    const int g  = lane >> 2, tg = lane & 3;

    float acc[MI][NI][4];
#pragma unroll
    for (int mi = 0; mi < MI; mi++)
#pragma unroll
        for (int ni = 0; ni < NI; ni++)
#pragma unroll
            for (int e = 0; e < 4; e++) acc[mi][ni][e] = 0.f;

    float4 aS[APT], bF0, bF1;

    // ---- prologue: stage chunk 0 into buffer 0 ----
#pragma unroll
    for (int i = 0; i < APT; i++) aS[i] = *(const float4*)(aptr[i]);
    if (bact) {
        bF0 = *(const float4*)(bptr0);
        bF1 = *(const float4*)(bptr0 + NF);
    }
#pragma unroll
    for (int i = 0; i < APT; i++) {
        uint2 hi, lo;
        split4(aS[i], hi, lo);
        *(uint2*)(sm + adst[i])       = hi;
        *(uint2*)(sm + adst[i] + APL) = lo;
    }
    if (bact) {
        uint4 hi, lo;
        packk4(bF0, bF1, hi, lo);
        *(uint4*)(sm + 2 * APL + bdst)        = hi;
        *(uint4*)(sm + 2 * APL + bdst + BPLP) = lo;
    }
    __syncthreads();

    for (int c = 0; c < NCH; c++) {
        // prefetch chunk c+1 (global latency overlaps the mma below)
        if (c + 1 < NCH) {
            const int k1 = (c + 1) * 16;
#pragma unroll
            for (int i = 0; i < APT; i++) aS[i] = *(const float4*)(aptr[i] + k1);
            if (bact) {
                const float* p = bptr0 + (size_t)k1 * NF;
                bF0 = *(const float4*)(p);
                bF1 = *(const float4*)(p + NF);
            }
        }

        const char* Ab = sm + (c & 1) * BUFSZ;
        const char* Bb = Ab + 2 * APL;

        // B fragments: single lds.32 per register from k-pair packed words
        uint32_t bh[NI][2], bl[NI][2];
#pragma unroll
        for (int ni = 0; ni < NI; ni++) {
            uint32_t w0 = (uint32_t)tg * BROWW + wn + ni * 8 + g;
            uint32_t w1 = w0 + 4 * BROWW;
            bh[ni][0] = *(const uint32_t*)(Bb + 4 * w0);
            bh[ni][1] = *(const uint32_t*)(Bb + 4 * w1);
            bl[ni][0] = *(const uint32_t*)(Bb + BPLP + 4 * w0);
            bl[ni][1] = *(const uint32_t*)(Bb + BPLP + 4 * w1);
        }

        // A fragments: hi plane first, MMA, then reuse the SAME regs for lo.
        uint32_t af[MI][4];
#pragma unroll
        for (int mi = 0; mi < MI; mi++) {
            uint32_t base = (uint32_t)(wm + mi * 16 + g) * ROWB + 4 * tg;
            af[mi][0] = *(const uint32_t*)(Ab + base);
            af[mi][1] = *(const uint32_t*)(Ab + base + 8 * ROWB);
            af[mi][2] = *(const uint32_t*)(Ab + base + 16);
            af[mi][3] = *(const uint32_t*)(Ab + base + 8 * ROWB + 16);
        }
#pragma unroll
        for (int mi = 0; mi < MI; mi++)
#pragma unroll
            for (int ni = 0; ni < NI; ni++) {
                MMA_BF16(acc[mi][ni], af[mi], bh[ni]);   // h*h
                MMA_BF16(acc[mi][ni], af[mi], bl[ni]);   // h*l
            }
#pragma unroll
        for (int mi = 0; mi < MI; mi++) {
            uint32_t base = (uint32_t)(wm + mi * 16 + g) * ROWB + 4 * tg + APL;
            af[mi][0] = *(const uint32_t*)(Ab + base);
            af[mi][1] = *(const uint32_t*)(Ab + base + 8 * ROWB);
            af[mi][2] = *(const uint32_t*)(Ab + base + 16);
            af[mi][3] = *(const uint32_t*)(Ab + base + 8 * ROWB + 16);
        }
#pragma unroll
        for (int mi = 0; mi < MI; mi++)
#pragma unroll
            for (int ni = 0; ni < NI; ni++)
                MMA_BF16(acc[mi][ni], af[mi], bh[ni]);   // l*h

        // store prefetched chunk into the other buffer
        if (c + 1 < NCH) {
            char* D = sm + ((c + 1) & 1) * BUFSZ;
#pragma unroll
            for (int i = 0; i < APT; i++) {
                uint2 hi, lo;
                split4(aS[i], hi, lo);
                *(uint2*)(D + adst[i])       = hi;
                *(uint2*)(D + adst[i] + APL) = lo;
            }
            if (bact) {
                uint4 hi, lo;
                packk4(bF0, bF1, hi, lo);
                *(uint4*)(D + 2 * APL + bdst)        = hi;
                *(uint4*)(D + 2 * APL + bdst + BPLP) = lo;
            }
        }
        __syncthreads();
    }

    // ----------------------------- epilogue (proven) -----------------------
    const float* bs = bias + (size_t)s * NF + n0;
    const float* gb = gbias + n0;
#pragma unroll
    for (int mi = 0; mi < MI; mi++) {
        const int rbase = wm + mi * 16 + g;
#pragma unroll
        for (int ni = 0; ni < NI; ni++) {
            const int c0 = wn + ni * 8 + 2 * tg;
            const float bv0 = bs[c0] + gb[c0];
            const float bv1 = bs[c0 + 1] + gb[c0 + 1];
#pragma unroll
            for (int half = 0; half < 2; half++) {
                const int r = rbase + half * 8;
                if (r < rows) {
                    float v0 = acc[mi][ni][half * 2 + 0] + bv0;
                    float v1 = acc[mi][ni][half * 2 + 1] + bv1;
                    if (RELU) { v0 = fmaxf(v0, 0.f); v1 = fmaxf(v1, 0.f); }
                    const int prow = off + m0 + r;
                    const int orow = (LAYER == 2) ? g_perm[prow] : prow;
                    *(float2*)(out + (size_t)orow * NF + n0 + c0) = make_float2(v0, v1);
                }
            }
        }
    }
}

// ---------------------------------------------------------------------------
extern "C" void kernel_launch(void* const* d_in, const int* in_sizes, int n_in,
                              void* d_out, int out_size) {
    const float* x     = (const float*)d_in[0];
    const int*   scene = (const int*)d_in[1];   // int32 or int64, auto-detected
    const float* W0  = (const float*)d_in[2];
    const float* b0  = (const float*)d_in[3];
    const float* gW0 = (const float*)d_in[4];
    const float* gb0 = (const float*)d_in[5];
    const float* W1  = (const float*)d_in[6];
    const float* b1  = (const float*)d_in[7];
    const float* gW1 = (const float*)d_in[8];
    const float* gb1 = (const float*)d_in[9];
    const float* W2  = (const float*)d_in[10];
    const float* b2  = (const float*)d_in[11];
    const float* gW2 = (const float*)d_in[12];
    const float* gb2 = (const float*)d_in[13];
    float* out = (float*)d_out;

    const int B = in_sizes[1];
    const int mt128 = (B + 127) / 128;
    const int mt64  = (B + 63) / 64;

    // smem: L0/L1: 2*(2*128*48 + 2*8*(128+8)*4) = 41984 (<48K, no opt-in)
    //       L2:    2*(2*64*48  + 2*8*(64+8)*4)  = 21504
    const int SM_L01 = 2 * (2 * 128 * 48 + 2 * 8 * (128 + 8) * 4);
    const int SM_L2  = 2 * (2 * 64 * 48 + 2 * 8 * (64 + 8) * 4);

    k_init<<<1, 32>>>();
    k_count<<<(B + 255) / 256, 256>>>(scene, B);
    k_scan<<<1, 1>>>();
    k_scatter<<<(B + 255) / 256, 256>>>(scene, B);
    k_scale_all<<<1024, 256>>>(W0, gW0, W1, gW1, W2, gW2);

    k_gemm<0, D0, D1, 128, 128, true ><<<dim3(mt128, D1 / 128, NS), 256, SM_L01>>>(
        x, nullptr, b0, gb0, B);
    k_gemm<1, D1, D2, 128, 128, true ><<<dim3(mt128, D2 / 128, NS), 256, SM_L01>>>(
        nullptr, nullptr, b1, gb1, B);
    k_gemm<2, D2, D3, 64, 64, false><<<dim3(mt64, 1, NS), 256, SM_L2>>>(
        nullptr, out, b2, gb2, B);
}